// round 10
// baseline (speedup 1.0000x reference)
#include <cuda_runtime.h>
#include <cuda_fp16.h>
#include <cstdint>

// Problem constants
#define HEADS   6
#define HD      32      // head_dim
#define DIMM    192
#define NWIN    256     // tokens per 16x16 window
#define KS_STRIDE 40    // half elements per K row in smem (80B rows, conflict-free)
#define VT_STRIDE 264   // half elements per Vt row in smem (528B rows, conflict-free)
#define LOG2E   1.4426950408889634f
#define QK_SCALE 0.17677669529663687f   // 32^-0.5

__device__ __forceinline__ float ex2f(float x) {
    float y;
    asm("ex2.approx.f32 %0, %1;" : "=f"(y) : "f"(x));
    return y;
}
__device__ __forceinline__ float rcpf(float x) {
    float y;
    asm("rcp.approx.f32 %0, %1;" : "=f"(y) : "f"(x));
    return y;
}

// pack two floats into f16x2 register: lo = first arg
__device__ __forceinline__ uint32_t pack_h2(float lo, float hi) {
    uint32_t r;
    asm("cvt.rn.f16x2.f32 %0, %1, %2;" : "=r"(r) : "f"(hi), "f"(lo));
    return r;
}

__device__ __forceinline__ uint32_t smem_u32(const void* p) {
    uint32_t a;
    asm("{ .reg .u64 t; cvta.to.shared.u64 t, %1; cvt.u32.u64 %0, t; }"
        : "=r"(a) : "l"(p));
    return a;
}

__device__ __forceinline__ void ldsm4(uint32_t* r, uint32_t addr) {
    asm volatile("ldmatrix.sync.aligned.m8n8.x4.shared.b16 {%0,%1,%2,%3}, [%4];"
        : "=r"(r[0]), "=r"(r[1]), "=r"(r[2]), "=r"(r[3]) : "r"(addr));
}

// D += A * B   (m16n8k16, f16 inputs, f32 accumulate) — non-volatile
#define MMA(c, a, bb)                                                         \
    asm("mma.sync.aligned.m16n8k16.row.col.f32.f16.f16.f32 "                  \
        "{%0,%1,%2,%3}, {%4,%5,%6,%7}, {%8,%9}, {%0,%1,%2,%3};"               \
        : "+f"((c)[0]), "+f"((c)[1]), "+f"((c)[2]), "+f"((c)[3])              \
        : "r"((a)[0]), "r"((a)[1]), "r"((a)[2]), "r"((a)[3]),                 \
          "r"((bb)[0]), "r"((bb)[1]))

__global__ __launch_bounds__(256, 2)
void winattn_kernel(const float* __restrict__ qkv,
                    const float* __restrict__ bias_table,
                    float* __restrict__ out)
{
    __shared__ half   Ks[NWIN * KS_STRIDE];   // 20480 B: K tile, row-major (n, k)
    __shared__ half   Vt[HD * VT_STRIDE];     // 16896 B: Vt[d][j] = V[j][d]
    __shared__ float2 bias2[961];             //  7688 B: (b[i], b[i+1]) * log2e

    const int tid  = threadIdx.x;
    const int bid  = blockIdx.x;
    const int head = bid % HEADS;
    const int win  = (bid / HEADS) & 255;
    const int b    = bid / (HEADS * 256);

    const int wh0 = (win >> 4) << 4;   // window top row in the image
    const int ww0 = (win & 15) << 4;   // window left col

    const long long plane = 65536LL * DIMM;

    // ---------------- load K, V into smem (fp16), bias pair table ---------
    {
        const float* kbase = qkv + (2 + b) * plane + head * HD;
        const float* vbase = qkv + (4 + b) * plane + head * HD;
        for (int vi = tid; vi < NWIN * (HD / 4); vi += 256) {
            const int p  = vi >> 3;            // window pixel 0..255
            const int c4 = (vi & 7) * 4;       // channel 0,4,...,28
            const int grow = (wh0 + (p >> 4)) * 256 + ww0 + (p & 15);
            const float4 kv = *(const float4*)(kbase + (long long)grow * DIMM + c4);
            const float4 vv = *(const float4*)(vbase + (long long)grow * DIMM + c4);
            *(half2*)&Ks[p * KS_STRIDE + c4]     = __floats2half2_rn(kv.x, kv.y);
            *(half2*)&Ks[p * KS_STRIDE + c4 + 2] = __floats2half2_rn(kv.z, kv.w);
            Vt[(c4 + 0) * VT_STRIDE + p] = __float2half_rn(vv.x);
            Vt[(c4 + 1) * VT_STRIDE + p] = __float2half_rn(vv.y);
            Vt[(c4 + 2) * VT_STRIDE + p] = __float2half_rn(vv.z);
            Vt[(c4 + 3) * VT_STRIDE + p] = __float2half_rn(vv.w);
        }
        for (int i = tid; i < 961; i += 256) {
            const float lo = bias_table[i * HEADS + head] * LOG2E;
            const int   in = (i < 960) ? i + 1 : 960;
            const float hi = bias_table[in * HEADS + head] * LOG2E;
            bias2[i] = make_float2(lo, hi);
        }
    }

    // ---------------- per-warp Q fragments (32 rows per warp) -------------
    const int warp  = tid >> 5;
    const int lane  = tid & 31;
    const int g     = lane >> 2;     // groupID 0..7
    const int t     = lane & 3;      // thread-in-group
    const int wbase = warp * 32;     // this warp's 32 query rows

    uint32_t af[2][2][4];            // [mtile][kstep][4 regs], Q * scale * log2e
    int ar0;                         // bias row code for mt0 row rA (mt1 = +31)
    {
        const float* qbase = qkv + b * plane + head * HD;
        const float qs = QK_SCALE * LOG2E;
        const int rA = wbase + g;
        ar0 = ((rA >> 4) + 15) * 31 + (rA & 15) + 15;
        #pragma unroll
        for (int mt = 0; mt < 2; mt++) {
            const int r0 = wbase + mt * 16 + g;
            const int r1 = r0 + 8;
            const int g0 = (wh0 + (r0 >> 4)) * 256 + ww0 + (r0 & 15);
            const int g1 = (wh0 + (r1 >> 4)) * 256 + ww0 + (r1 & 15);
            const float* qA = qbase + (long long)g0 * DIMM;
            const float* qB = qbase + (long long)g1 * DIMM;
            #pragma unroll
            for (int ks = 0; ks < 2; ks++) {
                const int c0 = ks * 16 + 2 * t;
                float2 f;
                f = *(const float2*)(qA + c0);
                af[mt][ks][0] = pack_h2(f.x * qs, f.y * qs);
                f = *(const float2*)(qB + c0);
                af[mt][ks][1] = pack_h2(f.x * qs, f.y * qs);
                f = *(const float2*)(qA + c0 + 8);
                af[mt][ks][2] = pack_h2(f.x * qs, f.y * qs);
                f = *(const float2*)(qB + c0 + 8);
                af[mt][ks][3] = pack_h2(f.x * qs, f.y * qs);
            }
        }
    }

    __syncthreads();

    // ---------------- ldmatrix base addresses ------------------------------
    const int lm = lane >> 3;   // matrix id within ldmatrix.x4
    const int lr = lane & 7;    // row within matrix
    uint32_t kaddr = smem_u32(&Ks[((lm >> 1) * 8 + lr) * KS_STRIDE + (lm & 1) * 8]);
    uint32_t vaddr = smem_u32(&Vt[((lm >> 1) * 8 + lr) * VT_STRIDE + (lm & 1) * 8]);
    const uint32_t voff2 = 16 * VT_STRIDE * 2;   // second V call: dt += 2
    const uint32_t KSTEP = 16 * KS_STRIDE * 2;   // 16 K rows

    // Bias pair-table index for mt0 (mt1 = +31):
    //   pairs needed: bias2[i00-8], bias2[i00], bias2[i00+8]
    int i00 = ar0 - (2 * t + 1);     // decrements by 31 each 16-col block

    float o[2][4][4] = {};    // [mtile][d-tile][4] fp32 accumulators
    float rs[2][2]   = {};    // row sums [mtile][half]

    // ---------------- main loop: 16-col K blocks, K double-buffered --------
    uint32_t bf[2][2][4];     // [parity][kstep][4]
    ldsm4(bf[0][0], kaddr);
    ldsm4(bf[0][1], kaddr + 32);
    kaddr += KSTEP;

    #pragma unroll 2
    for (int it = 0; it < 16; it++) {
        const int pc = it & 1, pn = pc ^ 1;

        // V fragments for this block
        uint32_t bv[8];
        ldsm4(bv,     vaddr);
        ldsm4(bv + 4, vaddr + voff2);
        vaddr += 32;

        // Prefetch next block's K (last iter overreads into Vt: in-bounds, unused)
        ldsm4(bf[pn][0], kaddr);
        ldsm4(bf[pn][1], kaddr + 32);
        kaddr += KSTEP;

        #pragma unroll
        for (int mt = 0; mt < 2; mt++) {
            const int ib = i00 + mt * 31;
            const float2 fm = bias2[ib];
            const float2 fh = bias2[ib + 8];
            const float2 fl = bias2[ib - 8];
            float s0[4], s1[4];
            s0[0] = fm.y; s0[1] = fm.x; s0[2] = fh.y; s0[3] = fh.x;
            s1[0] = fl.y; s1[1] = fl.x; s1[2] = fm.y; s1[3] = fm.x;

            // S = Q K^T + bias   (log2 units)
            MMA(s0, af[mt][0], &bf[pc][0][0]);
            MMA(s0, af[mt][1], &bf[pc][1][0]);
            MMA(s1, af[mt][0], &bf[pc][0][2]);
            MMA(s1, af[mt][1], &bf[pc][1][2]);

            // P = 2^S, packed straight into the PV A-fragment
            uint32_t pa[4];
            {
                const float p0 = ex2f(s0[0]);
                const float p1 = ex2f(s0[1]);
                const float p2 = ex2f(s0[2]);
                const float p3 = ex2f(s0[3]);
                rs[mt][0] += p0 + p1;
                rs[mt][1] += p2 + p3;
                pa[0] = pack_h2(p0, p1);
                pa[1] = pack_h2(p2, p3);
            }
            {
                const float p0 = ex2f(s1[0]);
                const float p1 = ex2f(s1[1]);
                const float p2 = ex2f(s1[2]);
                const float p3 = ex2f(s1[3]);
                rs[mt][0] += p0 + p1;
                rs[mt][1] += p2 + p3;
                pa[2] = pack_h2(p0, p1);
                pa[3] = pack_h2(p2, p3);
            }

            // O += P * V
            MMA(o[mt][0], pa, &bv[0]);
            MMA(o[mt][1], pa, &bv[2]);
            MMA(o[mt][2], pa, &bv[4]);
            MMA(o[mt][3], pa, &bv[6]);
        }

        i00 -= 31;
    }

    // ---------------- normalize and write output --------------------------
    #pragma unroll
    for (int mt = 0; mt < 2; mt++) {
        float r0 = rs[mt][0], r1 = rs[mt][1];
        r0 += __shfl_xor_sync(0xFFFFFFFFu, r0, 1);
        r0 += __shfl_xor_sync(0xFFFFFFFFu, r0, 2);
        r1 += __shfl_xor_sync(0xFFFFFFFFu, r1, 1);
        r1 += __shfl_xor_sync(0xFFFFFFFFu, r1, 2);
        const float inv0 = rcpf(r0);
        const float inv1 = rcpf(r1);

        const int rA = wbase + mt * 16 + g;
        const int rB = rA + 8;
        const long long gA = b * 65536LL + (wh0 + (rA >> 4)) * 256 + ww0 + (rA & 15);
        const long long gB = b * 65536LL + (wh0 + (rB >> 4)) * 256 + ww0 + (rB & 15);
        float* oA = out + gA * DIMM + head * HD;
        float* oB = out + gB * DIMM + head * HD;
        #pragma unroll
        for (int dt = 0; dt < 4; dt++) {
            const int d = dt * 8 + 2 * t;
            *(float2*)(oA + d) = make_float2(o[mt][dt][0] * inv0, o[mt][dt][1] * inv0);
            *(float2*)(oB + d) = make_float2(o[mt][dt][2] * inv1, o[mt][dt][3] * inv1);
        }
    }
}

extern "C" void kernel_launch(void* const* d_in, const int* in_sizes, int n_in,
                              void* d_out, int out_size)
{
    (void)in_sizes; (void)n_in; (void)out_size;
    const float* qkv        = (const float*)d_in[0];
    const float* bias_table = (const float*)d_in[1];
    float* out              = (float*)d_out;

    // 2 batches * 256 windows * 6 heads = 3072 CTAs, 256 threads each
    winattn_kernel<<<3072, 256>>>(qkv, bias_table, out);
}

// round 12
// speedup vs baseline: 1.3023x; 1.3023x over previous
#include <cuda_runtime.h>
#include <cuda_fp16.h>
#include <cstdint>

// Problem constants
#define HEADS   6
#define HD      32      // head_dim
#define DIMM    192
#define NWIN    256     // tokens per 16x16 window
#define KS_STRIDE 40    // half elements per K/V row in smem (80B rows, conflict-free)
#define LOG2E   1.4426950408889634f
#define QK_SCALE 0.17677669529663687f   // 32^-0.5

__device__ __forceinline__ float rcpf(float x) {
    float y; asm("rcp.approx.f32 %0, %1;" : "=f"(y) : "f"(x)); return y;
}
__device__ __forceinline__ uint32_t ex2h2(uint32_t a) {
    uint32_t d; asm("ex2.approx.f16x2 %0, %1;" : "=r"(d) : "r"(a)); return d;
}
__device__ __forceinline__ uint32_t hadd2u(uint32_t a, uint32_t b) {
    uint32_t d; asm("add.f16x2 %0, %1, %2;" : "=r"(d) : "r"(a), "r"(b)); return d;
}
__device__ __forceinline__ float2 h22f2(uint32_t h) {
    float2 f;
    asm("{\n\t.reg .f16 lo, hi;\n\tmov.b32 {lo, hi}, %2;\n\t"
        "cvt.f32.f16 %0, lo;\n\tcvt.f32.f16 %1, hi;\n\t}"
        : "=f"(f.x), "=f"(f.y) : "r"(h));
    return f;
}
// pack two floats into f16x2 register: lo = first arg
__device__ __forceinline__ uint32_t pack_h2(float lo, float hi) {
    uint32_t r;
    asm("cvt.rn.f16x2.f32 %0, %1, %2;" : "=r"(r) : "f"(hi), "f"(lo));
    return r;
}
__device__ __forceinline__ uint32_t smem_u32(const void* p) {
    uint32_t a;
    asm("{ .reg .u64 t; cvta.to.shared.u64 t, %1; cvt.u32.u64 %0, t; }"
        : "=r"(a) : "l"(p));
    return a;
}
__device__ __forceinline__ void ldsm4(uint32_t* r, uint32_t addr) {
    asm volatile("ldmatrix.sync.aligned.m8n8.x4.shared.b16 {%0,%1,%2,%3}, [%4];"
        : "=r"(r[0]), "=r"(r[1]), "=r"(r[2]), "=r"(r[3]) : "r"(addr));
}
__device__ __forceinline__ void ldsm4t(uint32_t* r, uint32_t addr) {
    asm volatile("ldmatrix.sync.aligned.m8n8.x4.trans.shared.b16 {%0,%1,%2,%3}, [%4];"
        : "=r"(r[0]), "=r"(r[1]), "=r"(r[2]), "=r"(r[3]) : "r"(addr));
}

// f16-accumulate MMA: {c0,c1} += A * B   (C/D are f16x2 pairs)
#define MMAH(c0, c1, a, b0, b1)                                               \
    asm("mma.sync.aligned.m16n8k16.row.col.f16.f16.f16.f16 "                  \
        "{%0,%1}, {%2,%3,%4,%5}, {%6,%7}, {%0,%1};"                           \
        : "+r"(c0), "+r"(c1)                                                  \
        : "r"((a)[0]), "r"((a)[1]), "r"((a)[2]), "r"((a)[3]),                 \
          "r"(b0), "r"(b1))

// f32-accumulate MMA: C += A * B
#define MMAF(c, a, b0, b1)                                                    \
    asm("mma.sync.aligned.m16n8k16.row.col.f32.f16.f16.f32 "                  \
        "{%0,%1,%2,%3}, {%4,%5,%6,%7}, {%8,%9}, {%0,%1,%2,%3};"               \
        : "+f"((c)[0]), "+f"((c)[1]), "+f"((c)[2]), "+f"((c)[3])              \
        : "r"((a)[0]), "r"((a)[1]), "r"((a)[2]), "r"((a)[3]),                 \
          "r"(b0), "r"(b1))

__global__ __launch_bounds__(512, 2)
void winattn_kernel(const float* __restrict__ qkv,
                    const float* __restrict__ bias_table,
                    float* __restrict__ out)
{
    __shared__ half     Ks[NWIN * KS_STRIDE];   // 20480 B: K, row-major (j, k)
    __shared__ half     Vs[NWIN * KS_STRIDE];   // 20480 B: V, row-major (j, d)
    __shared__ uint32_t bh[961];                //  3844 B: half2 (b[i+1], b[i]) * log2e

    const int tid  = threadIdx.x;
    const int bid  = blockIdx.x;
    const int head = bid % HEADS;
    const int win  = (bid / HEADS) & 255;
    const int b    = bid / (HEADS * 256);

    const int wh0 = (win >> 4) << 4;   // window top row in the image
    const int ww0 = (win & 15) << 4;   // window left col

    const long long plane = 65536LL * DIMM;

    // ---------------- load K, V into smem (fp16, identical layout) --------
    {
        const float* kbase = qkv + (2 + b) * plane + head * HD;
        const float* vbase = qkv + (4 + b) * plane + head * HD;
        for (int vi = tid; vi < NWIN * (HD / 4); vi += 512) {
            const int p  = vi >> 3;            // window pixel 0..255
            const int c4 = (vi & 7) * 4;       // channel 0,4,...,28
            const int grow = (wh0 + (p >> 4)) * 256 + ww0 + (p & 15);
            const float4 kv = *(const float4*)(kbase + (long long)grow * DIMM + c4);
            const float4 vv = *(const float4*)(vbase + (long long)grow * DIMM + c4);
            *(half2*)&Ks[p * KS_STRIDE + c4]     = __floats2half2_rn(kv.x, kv.y);
            *(half2*)&Ks[p * KS_STRIDE + c4 + 2] = __floats2half2_rn(kv.z, kv.w);
            *(half2*)&Vs[p * KS_STRIDE + c4]     = __floats2half2_rn(vv.x, vv.y);
            *(half2*)&Vs[p * KS_STRIDE + c4 + 2] = __floats2half2_rn(vv.z, vv.w);
        }
        // bias pair table as half2: .x (low) = b[i+1], .y (high) = b[i]
        for (int i = tid; i < 961; i += 512) {
            const float lo = bias_table[i * HEADS + head] * LOG2E;
            const float hi = (i < 960 ? bias_table[(i + 1) * HEADS + head] : 0.f) * LOG2E;
            bh[i] = pack_h2(hi, lo);   // low half = hi-index value
        }
    }

    // ---------------- per-warp Q fragments (16 rows per warp) -------------
    const int warp  = tid >> 5;
    const int lane  = tid & 31;
    const int g     = lane >> 2;     // groupID 0..7
    const int t     = lane & 3;      // thread-in-group
    const int wbase = warp * 16;     // this warp's 16 query rows

    uint32_t af[2][4];               // [kstep][4 regs], Q * scale * log2e
    int ar0;                         // bias row code for row rA (rB = +8)
    {
        const float* qbase = qkv + b * plane + head * HD;
        const float qs = QK_SCALE * LOG2E;
        const int rA = wbase + g;
        const int rB = rA + 8;
        ar0 = ((rA >> 4) + 15) * 31 + (rA & 15) + 15;
        const int gA = (wh0 + (rA >> 4)) * 256 + ww0 + (rA & 15);
        const int gB = (wh0 + (rB >> 4)) * 256 + ww0 + (rB & 15);
        const float* qA = qbase + (long long)gA * DIMM;
        const float* qB = qbase + (long long)gB * DIMM;
        #pragma unroll
        for (int ks = 0; ks < 2; ks++) {
            const int c0 = ks * 16 + 2 * t;
            float2 f;
            f = *(const float2*)(qA + c0);
            af[ks][0] = pack_h2(f.x * qs, f.y * qs);
            f = *(const float2*)(qB + c0);
            af[ks][1] = pack_h2(f.x * qs, f.y * qs);
            f = *(const float2*)(qA + c0 + 8);
            af[ks][2] = pack_h2(f.x * qs, f.y * qs);
            f = *(const float2*)(qB + c0 + 8);
            af[ks][3] = pack_h2(f.x * qs, f.y * qs);
        }
    }

    __syncthreads();

    // ---------------- fragment addresses (incremented per iter) -----------
    // K (non-trans x4): matrix m = lane>>3 -> tile (nt = m>>1, khalf = m&1)
    const int lm = lane >> 3;
    const int lr = lane & 7;
    uint32_t kaddr = smem_u32(&Ks[((lm >> 1) * 8 + lr) * KS_STRIDE + (lm & 1) * 8]);
    // V (trans x4): matrix m = lane>>3 = d-tile; row in tile = lane&7 = j row
    uint32_t vaddr = smem_u32(&Vs[(lane & 7) * KS_STRIDE + (lane >> 3) * 8]);
    const uint32_t VROW8 = 8 * KS_STRIDE * 2;    // +8 j rows
    const uint32_t JSTEP = 16 * KS_STRIDE * 2;   // +16 rows per iter

    // Bias pair-table index; decrements by 31 each 16-col block.
    int i00 = ar0 - (2 * t + 1);

    float o[4][4] = {};       // [d-tile][4] fp32 accumulators
    float rs0 = 0.f, rs1 = 0.f;

    // ---------------- main loop over 16-column K blocks -------------------
    #pragma unroll 1
    for (int it = 0; it < 16; it++) {
        // K fragments
        uint32_t bf[2][4];
        ldsm4(bf[0], kaddr);
        ldsm4(bf[1], kaddr + 32);
        // V fragments via ldmatrix.trans (k-low 8 rows, k-high 8 rows)
        uint32_t bvA[4], bvB[4];
        ldsm4t(bvA, vaddr);
        ldsm4t(bvB, vaddr + VROW8);

        // bias half2 pairs -> initialize f16 S accumulators
        uint32_t sc0 = bh[i00];          // (rA, cols c,c+1)
        uint32_t sc1 = bh[i00 + 8];      // (rB, cols c,c+1)
        uint32_t sc2 = bh[i00 - 8];      // (rA, cols c+8,c+9)
        uint32_t sc3 = bh[i00];          // (rB, cols c+8,c+9)

        // S = Q K^T + bias   (fp16 accum, log2 units)
        MMAH(sc0, sc1, af[0], bf[0][0], bf[0][1]);
        MMAH(sc0, sc1, af[1], bf[1][0], bf[1][1]);
        MMAH(sc2, sc3, af[0], bf[0][2], bf[0][3]);
        MMAH(sc2, sc3, af[1], bf[1][2], bf[1][3]);

        // P = 2^S  (f16x2) — C-frags ARE the PV A-frags
        uint32_t pa[4];
        pa[0] = ex2h2(sc0);
        pa[1] = ex2h2(sc1);
        pa[2] = ex2h2(sc2);
        pa[3] = ex2h2(sc3);

        // row sums: pairwise in fp16 (4 terms, exact-ish), accumulate fp32
        const float2 fA = h22f2(hadd2u(pa[0], pa[2]));
        rs0 += fA.x + fA.y;
        const float2 fB = h22f2(hadd2u(pa[1], pa[3]));
        rs1 += fB.x + fB.y;

        // O += P * V
        MMAF(o[0], pa, bvA[0], bvB[0]);
        MMAF(o[1], pa, bvA[1], bvB[1]);
        MMAF(o[2], pa, bvA[2], bvB[2]);
        MMAF(o[3], pa, bvA[3], bvB[3]);

        kaddr += JSTEP;
        vaddr += JSTEP;
        i00   -= 31;
    }

    // ---------------- normalize and write output --------------------------
    rs0 += __shfl_xor_sync(0xFFFFFFFFu, rs0, 1);
    rs0 += __shfl_xor_sync(0xFFFFFFFFu, rs0, 2);
    rs1 += __shfl_xor_sync(0xFFFFFFFFu, rs1, 1);
    rs1 += __shfl_xor_sync(0xFFFFFFFFu, rs1, 2);
    const float inv0 = rcpf(rs0);
    const float inv1 = rcpf(rs1);

    const int rA = wbase + g;
    const int rB = rA + 8;
    const long long gA = b * 65536LL + (wh0 + (rA >> 4)) * 256 + ww0 + (rA & 15);
    const long long gB = b * 65536LL + (wh0 + (rB >> 4)) * 256 + ww0 + (rB & 15);
    float* oA = out + gA * DIMM + head * HD;
    float* oB = out + gB * DIMM + head * HD;
    #pragma unroll
    for (int dt = 0; dt < 4; dt++) {
        const int d = dt * 8 + 2 * t;
        *(float2*)(oA + d) = make_float2(o[dt][0] * inv0, o[dt][1] * inv0);
        *(float2*)(oB + d) = make_float2(o[dt][2] * inv1, o[dt][3] * inv1);
    }
}

extern "C" void kernel_launch(void* const* d_in, const int* in_sizes, int n_in,
                              void* d_out, int out_size)
{
    (void)in_sizes; (void)n_in; (void)out_size;
    const float* qkv        = (const float*)d_in[0];
    const float* bias_table = (const float*)d_in[1];
    float* out              = (float*)d_out;

    // 2 batches * 256 windows * 6 heads = 3072 CTAs, 512 threads each
    winattn_kernel<<<3072, 512>>>(qkv, bias_table, out);
}